// round 15
// baseline (speedup 1.0000x reference)
#include <cuda_runtime.h>
#include <cuda_fp16.h>
#include <math.h>
#include <stdint.h>

#define BB 256
#define NN 256
#define DD 136
#define HH 128
#define ROWS (BB*NN)

#define K1PAD 152      // layer-1 K stride (304B rows -> conflict-free ldmatrix)
#define K2PAD 136      // layer-2 K stride (272B rows -> conflict-free)
#define TM    128      // rows per tile
#define NT    256      // 8 warps: 4 m-warps (m32) x 2 n-warps (n64)
#define GRID  296
#define NTILES (ROWS / TM)   // 512

// ---------------- scratch globals ----------------
__device__ __align__(16) float4 g_elg[ROWS];        // {exp(s), 1+log2(1+s), 2^label, 0}
__device__ __align__(16) __half g_W1t[HH * K1PAD];
__device__ __align__(16) __half g_W2t[HH * K2PAD];
__device__ unsigned long long g_bar = 0ULL;         // monotonic grid barrier

// ---------------- smem layout (113664 B/CTA -> 2 CTAs/SM) ----------------
#define A_BYTES  (TM * K1PAD * 2)           // 38912
#define W1_BYTES (128 * K1PAD * 2)          // 38912
#define W2_BYTES (128 * K2PAD * 2)          // 34816
#define OFF_A    0
#define OFF_RED  (TM * K2PAD * 2)           // 34816: A-tail, free during layer 2
#define OFF_W1   (A_BYTES)                  // 38912
#define OFF_W2   (OFF_W1 + W1_BYTES)        // 77824
#define OFF_B1   (OFF_W2 + W2_BYTES)        // 112640
#define OFF_B2   (OFF_B1 + 512)             // 113152
#define SMEM_BYTES (OFF_B2 + 512)           // 113664

__device__ __forceinline__ uint32_t smem_u32(const void* p) {
    uint32_t a;
    asm("{ .reg .u64 t; cvta.to.shared.u64 t, %1; cvt.u32.u64 %0, t; }" : "=r"(a) : "l"(p));
    return a;
}
__device__ __forceinline__ void cp_async16(uint32_t dst, const void* src) {
    asm volatile("cp.async.cg.shared.global [%0], [%1], 16;" :: "r"(dst), "l"(src));
}
#define CP_COMMIT() asm volatile("cp.async.commit_group;" ::: "memory")
#define CP_WAIT0()  asm volatile("cp.async.wait_group 0;" ::: "memory")

__device__ __forceinline__ void ldsm_x4(uint32_t* r, uint32_t addr) {
    asm volatile("ldmatrix.sync.aligned.m8n8.x4.shared.b16 {%0,%1,%2,%3}, [%4];"
        : "=r"(r[0]), "=r"(r[1]), "=r"(r[2]), "=r"(r[3]) : "r"(addr));
}
__device__ __forceinline__ void mma16816(float* d, const uint32_t* a, uint32_t b0, uint32_t b1) {
    asm volatile("mma.sync.aligned.m16n8k16.row.col.f32.f16.f16.f32 "
        "{%0,%1,%2,%3}, {%4,%5,%6,%7}, {%8,%9}, {%0,%1,%2,%3};"
        : "+f"(d[0]), "+f"(d[1]), "+f"(d[2]), "+f"(d[3])
        : "r"(a[0]), "r"(a[1]), "r"(a[2]), "r"(a[3]), "r"(b0), "r"(b1));
}
__device__ __forceinline__ uint32_t pack_h2(float x, float y) {
    __half h0 = __float2half_rn(x), h1 = __float2half_rn(y);
    return ((uint32_t)__half_as_ushort(h1) << 16) | __half_as_ushort(h0);
}

// ---------------- persistent MLP: prep + barrier + tile loop (m32n64 warps) ----------------
__global__ __launch_bounds__(NT, 2)
void mlp_persist(const float* __restrict__ feat, const int* __restrict__ labels,
                 const float* __restrict__ W1, const float* __restrict__ b1,
                 const float* __restrict__ W2, const float* __restrict__ b2,
                 const float* __restrict__ W3, const float* __restrict__ b3)
{
    extern __shared__ char smem[];
    __half* A  = (__half*)(smem + OFF_A);
    float* sB1 = (float*)(smem + OFF_B1);
    float* sB2 = (float*)(smem + OFF_B2);
    float* red = (float*)(smem + OFF_RED);   // 256 floats, A-tail

    const int tid  = threadIdx.x;
    const int lane = tid & 31;
    const int wid  = tid >> 5;
    const int m0    = (wid >> 1) * 32;       // 0,32,64,96
    const int nside = (wid & 1) * 64;

    const uint32_t uA  = smem_u32(smem + OFF_A);
    const uint32_t uW1 = smem_u32(smem + OFF_W1);
    const uint32_t uW2 = smem_u32(smem + OFF_W2);

    const int a_row = m0 + (lane & 7) + ((lane >> 3) & 1) * 8;   // frag0; frag1 = +16
    const int a_kof = (lane >> 4) * 8;
    const int w_rof = (lane & 7) + (lane >> 4) * 8;
    const int w_kof = ((lane >> 3) & 1) * 8;

    // ===== phase 0: weight prep (grid-strided), then global barrier =====
    for (int idx = blockIdx.x * NT + tid; idx < 152 * 32 + 128 * 32; idx += GRID * NT) {
        if (idx < 152 * 32) {
            int k = idx >> 5, nq = (idx & 31) * 4;
            float4 v = (k < DD) ? *(const float4*)(W1 + k * HH + nq)
                                : make_float4(0.f, 0.f, 0.f, 0.f);
            g_W1t[(nq + 0) * K1PAD + k] = __float2half_rn(v.x);
            g_W1t[(nq + 1) * K1PAD + k] = __float2half_rn(v.y);
            g_W1t[(nq + 2) * K1PAD + k] = __float2half_rn(v.z);
            g_W1t[(nq + 3) * K1PAD + k] = __float2half_rn(v.w);
        } else {
            int idx2 = idx - 152 * 32;
            int k = idx2 >> 5, nq = (idx2 & 31) * 4;
            float4 v = *(const float4*)(W2 + k * HH + nq);
            g_W2t[(nq + 0) * K2PAD + k] = __float2half_rn(v.x);
            g_W2t[(nq + 1) * K2PAD + k] = __float2half_rn(v.y);
            g_W2t[(nq + 2) * K2PAD + k] = __float2half_rn(v.z);
            g_W2t[(nq + 3) * K2PAD + k] = __float2half_rn(v.w);
        }
    }
    __threadfence();
    __syncthreads();
    if (tid == 0) {
        unsigned long long old = atomicAdd(&g_bar, 1ULL);
        unsigned long long target = (old / GRID + 1ULL) * GRID;
        unsigned long long v;
        do {
            asm volatile("ld.acquire.gpu.global.u64 %0, [%1];" : "=l"(v) : "l"(&g_bar));
        } while (v < target);
    }
    __syncthreads();

    // ===== stage weights to smem ONCE =====
    {
        const char* s;
        s = (const char*)g_W1t;
        for (int i = tid; i < W1_BYTES / 16; i += NT) cp_async16(uW1 + i * 16, s + i * 16);
        s = (const char*)g_W2t;
        for (int i = tid; i < W2_BYTES / 16; i += NT) cp_async16(uW2 + i * 16, s + i * 16);
        CP_COMMIT();
    }
    if (tid < 128) { sB1[tid] = b1[tid]; sB2[tid] = b2[tid]; }
    const float b3v = __ldg(b3);
    CP_WAIT0();
    __syncthreads();

    // ===== persistent tile loop =====
    for (int tile = blockIdx.x; tile < NTILES; tile += GRID) {
        const long row0 = (long)tile * TM;

        // ---- stage features -> fp16 (128 rows, 2 threads/row, 34 pairs each) ----
        {
            const int r = tid >> 1, h = tid & 1;
            const float2* fb = (const float2*)(feat + (row0 + r) * DD) + 34 * h;
            #pragma unroll
            for (int it = 0; it < 34; it++) {
                float2 vv = fb[it];
                const int p = 34 * h + it;
                *(uint32_t*)(A + r * K1PAD + 2 * p) = pack_h2(vv.x, vv.y);
            }
            #pragma unroll
            for (int q = 0; q < 4; q++) {
                const int p = 68 + h * 4 + q;
                *(uint32_t*)(A + r * K1PAD + 2 * p) = 0;
            }
        }
        __syncthreads();

        float acc0[8][4], acc1[8][4];
        #pragma unroll
        for (int t = 0; t < 8; t++)
            #pragma unroll
            for (int q = 0; q < 4; q++) { acc0[t][q] = 0.f; acc1[t][q] = 0.f; }

        // ---- layer 1: 9 ksteps, m32n64 ----
        #pragma unroll
        for (int ks = 0; ks < 9; ks++) {
            const int k0 = ks * 16;
            uint32_t a0[4], a1[4];
            ldsm_x4(a0, uA + (a_row * K1PAD + k0 + a_kof) * 2);
            ldsm_x4(a1, uA + ((a_row + 16) * K1PAD + k0 + a_kof) * 2);
            #pragma unroll
            for (int np = 0; np < 4; np++) {
                const int n0 = nside + np * 16;
                uint32_t w[4];
                ldsm_x4(w, uW1 + ((n0 + w_rof) * K1PAD + k0 + w_kof) * 2);
                mma16816(acc0[2*np],   a0, w[0], w[1]);
                mma16816(acc0[2*np+1], a0, w[2], w[3]);
                mma16816(acc1[2*np],   a1, w[0], w[1]);
                mma16816(acc1[2*np+1], a1, w[2], w[3]);
            }
        }
        __syncthreads();

        // ---- epilogue 1: relu(+b1) -> fp16 into A, stride K2PAD ----
        {
            const int rA = m0 + (lane >> 2);
            #pragma unroll
            for (int nt = 0; nt < 8; nt++) {
                const int c = nside + nt * 8 + (lane & 3) * 2;
                const float bc0 = sB1[c], bc1 = sB1[c + 1];
                float v0 = fmaxf(acc0[nt][0] + bc0, 0.f);
                float v1 = fmaxf(acc0[nt][1] + bc1, 0.f);
                float v2 = fmaxf(acc0[nt][2] + bc0, 0.f);
                float v3 = fmaxf(acc0[nt][3] + bc1, 0.f);
                float u0 = fmaxf(acc1[nt][0] + bc0, 0.f);
                float u1 = fmaxf(acc1[nt][1] + bc1, 0.f);
                float u2 = fmaxf(acc1[nt][2] + bc0, 0.f);
                float u3 = fmaxf(acc1[nt][3] + bc1, 0.f);
                *(uint32_t*)(A + rA * K2PAD + c)        = pack_h2(v0, v1);
                *(uint32_t*)(A + (rA + 8) * K2PAD + c)  = pack_h2(v2, v3);
                *(uint32_t*)(A + (rA + 16) * K2PAD + c) = pack_h2(u0, u1);
                *(uint32_t*)(A + (rA + 24) * K2PAD + c) = pack_h2(u2, u3);
            }
        }
        __syncthreads();

        #pragma unroll
        for (int t = 0; t < 8; t++)
            #pragma unroll
            for (int q = 0; q < 4; q++) { acc0[t][q] = 0.f; acc1[t][q] = 0.f; }

        // ---- layer 2: 8 ksteps, m32n64 ----
        #pragma unroll
        for (int ks = 0; ks < 8; ks++) {
            const int k0 = ks * 16;
            uint32_t a0[4], a1[4];
            ldsm_x4(a0, uA + (a_row * K2PAD + k0 + a_kof) * 2);
            ldsm_x4(a1, uA + ((a_row + 16) * K2PAD + k0 + a_kof) * 2);
            #pragma unroll
            for (int np = 0; np < 4; np++) {
                const int n0 = nside + np * 16;
                uint32_t w[4];
                ldsm_x4(w, uW2 + ((n0 + w_rof) * K2PAD + k0 + w_kof) * 2);
                mma16816(acc0[2*np],   a0, w[0], w[1]);
                mma16816(acc0[2*np+1], a0, w[2], w[3]);
                mma16816(acc1[2*np],   a1, w[0], w[1]);
                mma16816(acc1[2*np+1], a1, w[2], w[3]);
            }
        }

        // ---- epilogue 2: relu(+b2).W3 -> red (A-tail, disjoint from live h1) ----
        {
            float p0 = 0.f, p1 = 0.f, p2 = 0.f, p3 = 0.f;
            #pragma unroll
            for (int nt = 0; nt < 8; nt++) {
                const int c = nside + nt * 8 + (lane & 3) * 2;
                const float bc0 = sB2[c],       bc1 = sB2[c + 1];
                const float w0  = __ldg(W3 + c), w1 = __ldg(W3 + c + 1);
                p0 = fmaf(fmaxf(acc0[nt][0] + bc0, 0.f), w0, p0);
                p0 = fmaf(fmaxf(acc0[nt][1] + bc1, 0.f), w1, p0);
                p1 = fmaf(fmaxf(acc0[nt][2] + bc0, 0.f), w0, p1);
                p1 = fmaf(fmaxf(acc0[nt][3] + bc1, 0.f), w1, p1);
                p2 = fmaf(fmaxf(acc1[nt][0] + bc0, 0.f), w0, p2);
                p2 = fmaf(fmaxf(acc1[nt][1] + bc1, 0.f), w1, p2);
                p3 = fmaf(fmaxf(acc1[nt][2] + bc0, 0.f), w0, p3);
                p3 = fmaf(fmaxf(acc1[nt][3] + bc1, 0.f), w1, p3);
            }
            #pragma unroll
            for (int d = 1; d <= 2; d <<= 1) {
                p0 += __shfl_xor_sync(0xFFFFFFFF, p0, d);
                p1 += __shfl_xor_sync(0xFFFFFFFF, p1, d);
                p2 += __shfl_xor_sync(0xFFFFFFFF, p2, d);
                p3 += __shfl_xor_sync(0xFFFFFFFF, p3, d);
            }
            if ((lane & 3) == 0) {
                const int rr = m0 + (lane >> 2);
                red[rr * 2 + (wid & 1)]        = p0;
                red[(rr + 8) * 2 + (wid & 1)]  = p1;
                red[(rr + 16) * 2 + (wid & 1)] = p2;
                red[(rr + 24) * 2 + (wid & 1)] = p3;
            }
        }
        __syncthreads();
        if (tid < TM) {
            float s = red[tid * 2] + red[tid * 2 + 1] + b3v;
            int   l = labels[row0 + tid];
            float e = __expf(s);
            float M = 1.0f + __log2f(1.0f + s);
            float g = __int_as_float((l + 127) << 23);   // 2^l exactly
            g_elg[row0 + tid] = make_float4(e, M, g, 0.f);
        }
        __syncthreads();   // red reads done before next tile's staging overwrites A
    }
}

// ---------------- lambda kernel: 8 blocks/batch (R13 verbatim) ----------------
__global__ __launch_bounds__(256, 8)
void lambda_kernel(float* __restrict__ out)
{
    __shared__ float4 elg[NN];
    __shared__ float  part[256];

    const int bid   = blockIdx.x;        // 0..2047
    const int batch = bid >> 3;
    const int io    = bid & 7;
    const int tid   = threadIdx.x;
    const int il    = tid & 31;
    const int jh    = tid >> 5;

    elg[tid] = g_elg[batch * NN + tid];
    __syncthreads();

    const int i = io * 32 + il;
    const float4 me = elg[i];
    const float ei = me.x, Mi = me.y, gi = me.z;

    float acc0 = 0.f, acc1 = 0.f;
    const int j0 = jh * 32;
    #pragma unroll 4
    for (int j = 0; j < 32; j += 2) {
        float4 va = elg[j0 + j];
        float4 vb = elg[j0 + j + 1];
        float sga = gi - va.z;
        float sgb = gi - vb.z;
        float ta = (sga > 0.f) ? ei : va.x;
        float tb = (sgb > 0.f) ? ei : vb.x;
        acc0 += __fdividef(sga * ta, fabsf(fmaxf(Mi, va.y)) * (ei + va.x));
        acc1 += __fdividef(sgb * tb, fabsf(fmaxf(Mi, vb.y)) * (ei + vb.x));
    }
    part[tid] = acc0 + acc1;
    __syncthreads();
    if (tid < 32) {
        float s = 0.f;
        #pragma unroll
        for (int k = 0; k < 8; k++) s += part[tid + 32 * k];
        out[batch * NN + io * 32 + tid] = 0.5f * s;
    }
}

extern "C" void kernel_launch(void* const* d_in, const int* in_sizes, int n_in,
                              void* d_out, int out_size)
{
    const float* feat   = (const float*)d_in[0];
    const int*   labels = (const int*)d_in[1];
    const float* W1 = (const float*)d_in[2];
    const float* b1 = (const float*)d_in[3];
    const float* W2 = (const float*)d_in[4];
    const float* b2 = (const float*)d_in[5];
    const float* W3 = (const float*)d_in[6];
    const float* b3 = (const float*)d_in[7];
    float* out = (float*)d_out;

    static bool attr_set = false;
    if (!attr_set) {
        cudaFuncSetAttribute(mlp_persist, cudaFuncAttributeMaxDynamicSharedMemorySize,
                             (int)SMEM_BYTES);
        attr_set = true;
    }

    mlp_persist<<<GRID, NT, SMEM_BYTES>>>(feat, labels, W1, b1, W2, b2, W3, b3);
    lambda_kernel<<<8 * BB, 256>>>(out);
}

// round 16
// speedup vs baseline: 1.6119x; 1.6119x over previous
#include <cuda_runtime.h>
#include <cuda_fp16.h>
#include <math.h>
#include <stdint.h>

#define BB 256
#define NN 256
#define DD 136
#define HH 128
#define ROWS (BB*NN)

#define K1PAD 152
#define K2PAD 136
#define TM    64
#define NT    256
#define GRID  296
#define NTILES (ROWS / TM)   // 1024

// ---------------- scratch globals ----------------
__device__ __align__(16) float4 g_elg[ROWS];        // {exp(s), 1+log2(1+s), 2^label, 0}
__device__ __align__(16) __half g_W1t[HH * K1PAD];
__device__ __align__(16) __half g_W2t[HH * K2PAD];
__device__ unsigned long long g_bar = 0ULL;         // monotonic grid barrier

// ---------------- smem layout ----------------
#define A_BYTES  (TM * K1PAD * 2)           // 19456
#define W1_BYTES (128 * K1PAD * 2)
#define W2_BYTES (128 * K2PAD * 2)
#define OFF_A    0
#define OFF_W1   (A_BYTES)
#define OFF_W2   (OFF_W1 + W1_BYTES)
#define OFF_B1   (OFF_W2 + W2_BYTES)        // 93184
#define OFF_B2   (OFF_B1 + 512)
#define OFF_W3   (OFF_B2 + 512)
#define OFF_RED  (OFF_W3 + 512)
#define SMEM_BYTES (OFF_RED + 512)          // 95232 (x2 CTAs < 227KB)

__device__ __forceinline__ uint32_t smem_u32(const void* p) {
    uint32_t a;
    asm("{ .reg .u64 t; cvta.to.shared.u64 t, %1; cvt.u32.u64 %0, t; }" : "=r"(a) : "l"(p));
    return a;
}
__device__ __forceinline__ void cp_async16(uint32_t dst, const void* src) {
    asm volatile("cp.async.cg.shared.global [%0], [%1], 16;" :: "r"(dst), "l"(src));
}
#define CP_COMMIT() asm volatile("cp.async.commit_group;" ::: "memory")
#define CP_WAIT0()  asm volatile("cp.async.wait_group 0;" ::: "memory")

__device__ __forceinline__ void ldsm_x4(uint32_t* r, uint32_t addr) {
    asm volatile("ldmatrix.sync.aligned.m8n8.x4.shared.b16 {%0,%1,%2,%3}, [%4];"
        : "=r"(r[0]), "=r"(r[1]), "=r"(r[2]), "=r"(r[3]) : "r"(addr));
}
__device__ __forceinline__ void mma16816(float* d, const uint32_t* a, uint32_t b0, uint32_t b1) {
    asm volatile("mma.sync.aligned.m16n8k16.row.col.f32.f16.f16.f32 "
        "{%0,%1,%2,%3}, {%4,%5,%6,%7}, {%8,%9}, {%0,%1,%2,%3};"
        : "+f"(d[0]), "+f"(d[1]), "+f"(d[2]), "+f"(d[3])
        : "r"(a[0]), "r"(a[1]), "r"(a[2]), "r"(a[3]), "r"(b0), "r"(b1));
}
__device__ __forceinline__ uint32_t pack_h2(float x, float y) {
    __half h0 = __float2half_rn(x), h1 = __float2half_rn(y);
    return ((uint32_t)__half_as_ushort(h1) << 16) | __half_as_ushort(h0);
}

// ---------------- persistent fused MLP (R13 verbatim) ----------------
__global__ __launch_bounds__(NT, 2)
void mlp_persist(const float* __restrict__ feat, const int* __restrict__ labels,
                 const float* __restrict__ W1, const float* __restrict__ b1,
                 const float* __restrict__ W2, const float* __restrict__ b2,
                 const float* __restrict__ W3, const float* __restrict__ b3)
{
    extern __shared__ char smem[];
    __half* A  = (__half*)(smem + OFF_A);
    float* sB1 = (float*)(smem + OFF_B1);
    float* sB2 = (float*)(smem + OFF_B2);
    float* sW3 = (float*)(smem + OFF_W3);
    float* red = (float*)(smem + OFF_RED);

    const int tid  = threadIdx.x;
    const int lane = tid & 31;
    const int wid  = tid >> 5;
    const int m0    = (wid >> 1) * 16;
    const int nside = (wid & 1) * 64;

    const uint32_t uA  = smem_u32(smem + OFF_A);
    const uint32_t uW1 = smem_u32(smem + OFF_W1);
    const uint32_t uW2 = smem_u32(smem + OFF_W2);

    const int a_row = m0 + (lane & 7) + ((lane >> 3) & 1) * 8;
    const int a_kof = (lane >> 4) * 8;
    const int w_rof = (lane & 7) + (lane >> 4) * 8;
    const int w_kof = ((lane >> 3) & 1) * 8;

    // ===== phase 0: weight prep (grid-strided), then global barrier =====
    for (int idx = blockIdx.x * NT + tid; idx < 152 * 32 + 128 * 32; idx += GRID * NT) {
        if (idx < 152 * 32) {
            int k = idx >> 5, nq = (idx & 31) * 4;
            float4 v = (k < DD) ? *(const float4*)(W1 + k * HH + nq)
                                : make_float4(0.f, 0.f, 0.f, 0.f);
            g_W1t[(nq + 0) * K1PAD + k] = __float2half_rn(v.x);
            g_W1t[(nq + 1) * K1PAD + k] = __float2half_rn(v.y);
            g_W1t[(nq + 2) * K1PAD + k] = __float2half_rn(v.z);
            g_W1t[(nq + 3) * K1PAD + k] = __float2half_rn(v.w);
        } else {
            int idx2 = idx - 152 * 32;
            int k = idx2 >> 5, nq = (idx2 & 31) * 4;
            float4 v = *(const float4*)(W2 + k * HH + nq);
            g_W2t[(nq + 0) * K2PAD + k] = __float2half_rn(v.x);
            g_W2t[(nq + 1) * K2PAD + k] = __float2half_rn(v.y);
            g_W2t[(nq + 2) * K2PAD + k] = __float2half_rn(v.z);
            g_W2t[(nq + 3) * K2PAD + k] = __float2half_rn(v.w);
        }
    }
    __threadfence();
    __syncthreads();
    if (tid == 0) {
        unsigned long long old = atomicAdd(&g_bar, 1ULL);
        unsigned long long target = (old / GRID + 1ULL) * GRID;
        unsigned long long v;
        do {
            asm volatile("ld.acquire.gpu.global.u64 %0, [%1];" : "=l"(v) : "l"(&g_bar));
        } while (v < target);
    }
    __syncthreads();

    // ===== stage weights to smem ONCE =====
    {
        const char* s;
        s = (const char*)g_W1t;
        for (int i = tid; i < W1_BYTES / 16; i += NT) cp_async16(uW1 + i * 16, s + i * 16);
        s = (const char*)g_W2t;
        for (int i = tid; i < W2_BYTES / 16; i += NT) cp_async16(uW2 + i * 16, s + i * 16);
        CP_COMMIT();
    }
    if (tid < 128) { sB1[tid] = b1[tid]; sB2[tid] = b2[tid]; sW3[tid] = W3[tid]; }
    const float b3v = __ldg(b3);
    CP_WAIT0();
    __syncthreads();

    // ===== pipelined persistent tile loop =====
    const int r  = tid >> 2;
    const int c4 = tid & 3;
    float2 v[17];
    {   // initial prefetch
        const float* fb = feat + ((long)blockIdx.x * TM + r) * DD + 2 * c4;
        #pragma unroll
        for (int it = 0; it < 17; it++) v[it] = *(const float2*)(fb + 8 * it);
    }

    for (int tile = blockIdx.x; tile < NTILES; tile += GRID) {
        const long row0 = (long)tile * TM;

        // ---- store prefetched features -> fp16 A ----
        #pragma unroll
        for (int it = 0; it < 17; it++) {
            const int p = c4 + 4 * it;
            *(uint32_t*)(A + r * K1PAD + 2 * p) = pack_h2(v[it].x, v[it].y);
        }
        *(uint32_t*)(A + r * K1PAD + 2 * (68 + c4)) = 0;
        *(uint32_t*)(A + r * K1PAD + 2 * (72 + c4)) = 0;
        __syncthreads();

        // ---- prefetch next tile's features ----
        {
            const int nxt = tile + GRID;
            if (nxt < NTILES) {
                const float* fb = feat + ((long)nxt * TM + r) * DD + 2 * c4;
                #pragma unroll
                for (int it = 0; it < 17; it++) v[it] = *(const float2*)(fb + 8 * it);
            }
        }

        float acc[8][4];
        #pragma unroll
        for (int t = 0; t < 8; t++)
            #pragma unroll
            for (int q = 0; q < 4; q++) acc[t][q] = 0.f;

        // ---- layer 1: 9 ksteps ----
        #pragma unroll
        for (int ks = 0; ks < 9; ks++) {
            const int k0 = ks * 16;
            uint32_t a[4];
            ldsm_x4(a, uA + (a_row * K1PAD + k0 + a_kof) * 2);
            #pragma unroll
            for (int np = 0; np < 4; np++) {
                const int n0 = nside + np * 16;
                uint32_t w[4];
                ldsm_x4(w, uW1 + ((n0 + w_rof) * K1PAD + k0 + w_kof) * 2);
                mma16816(acc[2*np],   a, w[0], w[1]);
                mma16816(acc[2*np+1], a, w[2], w[3]);
            }
        }
        __syncthreads();

        // ---- epilogue 1 ----
        {
            const int rA = m0 + (lane >> 2);
            #pragma unroll
            for (int nt = 0; nt < 8; nt++) {
                const int c = nside + nt * 8 + (lane & 3) * 2;
                float v0 = fmaxf(acc[nt][0] + sB1[c],     0.f);
                float v1 = fmaxf(acc[nt][1] + sB1[c + 1], 0.f);
                float v2 = fmaxf(acc[nt][2] + sB1[c],     0.f);
                float v3 = fmaxf(acc[nt][3] + sB1[c + 1], 0.f);
                *(uint32_t*)(A + rA * K2PAD + c)       = pack_h2(v0, v1);
                *(uint32_t*)(A + (rA + 8) * K2PAD + c) = pack_h2(v2, v3);
            }
        }
        __syncthreads();

        #pragma unroll
        for (int t = 0; t < 8; t++)
            #pragma unroll
            for (int q = 0; q < 4; q++) acc[t][q] = 0.f;

        // ---- layer 2: 8 ksteps ----
        #pragma unroll
        for (int ks = 0; ks < 8; ks++) {
            const int k0 = ks * 16;
            uint32_t a[4];
            ldsm_x4(a, uA + (a_row * K2PAD + k0 + a_kof) * 2);
            #pragma unroll
            for (int np = 0; np < 4; np++) {
                const int n0 = nside + np * 16;
                uint32_t w[4];
                ldsm_x4(w, uW2 + ((n0 + w_rof) * K2PAD + k0 + w_kof) * 2);
                mma16816(acc[2*np],   a, w[0], w[1]);
                mma16816(acc[2*np+1], a, w[2], w[3]);
            }
        }

        // ---- epilogue 2: relu(+b2).W3, reduce, fused elg write ----
        {
            float pl = 0.f, ph = 0.f;
            #pragma unroll
            for (int nt = 0; nt < 8; nt++) {
                const int c = nside + nt * 8 + (lane & 3) * 2;
                pl = fmaf(fmaxf(acc[nt][0] + sB2[c],     0.f), sW3[c],     pl);
                pl = fmaf(fmaxf(acc[nt][1] + sB2[c + 1], 0.f), sW3[c + 1], pl);
                ph = fmaf(fmaxf(acc[nt][2] + sB2[c],     0.f), sW3[c],     ph);
                ph = fmaf(fmaxf(acc[nt][3] + sB2[c + 1], 0.f), sW3[c + 1], ph);
            }
            pl += __shfl_xor_sync(0xFFFFFFFF, pl, 1);
            pl += __shfl_xor_sync(0xFFFFFFFF, pl, 2);
            ph += __shfl_xor_sync(0xFFFFFFFF, ph, 1);
            ph += __shfl_xor_sync(0xFFFFFFFF, ph, 2);
            if ((lane & 3) == 0) {
                const int rr = m0 + (lane >> 2);
                red[rr * 2 + (wid & 1)]       = pl;
                red[(rr + 8) * 2 + (wid & 1)] = ph;
            }
        }
        __syncthreads();
        if (tid < TM) {
            float s = red[tid * 2] + red[tid * 2 + 1] + b3v;
            int   l = labels[row0 + tid];
            float e = __expf(s);
            float M = 1.0f + __log2f(1.0f + s);
            float g = __int_as_float((l + 127) << 23);   // 2^l exactly
            g_elg[row0 + tid] = make_float4(e, M, g, 0.f);
        }
        __syncthreads();
    }
}

// ---------------- lambda kernel: 8 blocks/batch, 4-pair fraction combine ----------------
__global__ __launch_bounds__(256, 8)
void lambda_kernel(float* __restrict__ out)
{
    __shared__ float4 elg[NN];
    __shared__ float  part[256];

    const int bid   = blockIdx.x;        // 0..2047
    const int batch = bid >> 3;
    const int io    = bid & 7;
    const int tid   = threadIdx.x;
    const int il    = tid & 31;
    const int jh    = tid >> 5;

    elg[tid] = g_elg[batch * NN + tid];
    __syncthreads();

    const int i = io * 32 + il;
    const float4 me = elg[i];
    const float ei = me.x, Mi = me.y, gi = me.z;

    float acc = 0.f;
    const int j0 = jh * 32;
    #pragma unroll 2
    for (int j = 0; j < 32; j += 4) {
        float4 v0 = elg[j0 + j];
        float4 v1 = elg[j0 + j + 1];
        float4 v2 = elg[j0 + j + 2];
        float4 v3 = elg[j0 + j + 3];
        // per-pair numerator & (non-negative) denominator
        float sg0 = gi - v0.z, sg1 = gi - v1.z, sg2 = gi - v2.z, sg3 = gi - v3.z;
        float n0 = sg0 * ((sg0 > 0.f) ? ei : v0.x);
        float n1 = sg1 * ((sg1 > 0.f) ? ei : v1.x);
        float n2 = sg2 * ((sg2 > 0.f) ? ei : v2.x);
        float n3 = sg3 * ((sg3 > 0.f) ? ei : v3.x);
        float d0 = fabsf(fmaxf(Mi, v0.y)) * (ei + v0.x);
        float d1 = fabsf(fmaxf(Mi, v1.y)) * (ei + v1.x);
        float d2 = fabsf(fmaxf(Mi, v2.y)) * (ei + v2.x);
        float d3 = fabsf(fmaxf(Mi, v3.y)) * (ei + v3.x);
        // combine 4 fractions into 1 division (all d >= 0)
        float d01 = d0 * d1, d23 = d2 * d3;
        float t01 = fmaf(n0, d1, n1 * d0);
        float t23 = fmaf(n2, d3, n3 * d2);
        float num = fmaf(t01, d23, t23 * d01);
        float den = d01 * d23;
        acc += __fdividef(num, den);
    }
    part[tid] = acc;
    __syncthreads();
    if (tid < 32) {
        float s = 0.f;
        #pragma unroll
        for (int k = 0; k < 8; k++) s += part[tid + 32 * k];
        out[batch * NN + io * 32 + tid] = 0.5f * s;
    }
}

extern "C" void kernel_launch(void* const* d_in, const int* in_sizes, int n_in,
                              void* d_out, int out_size)
{
    const float* feat   = (const float*)d_in[0];
    const int*   labels = (const int*)d_in[1];
    const float* W1 = (const float*)d_in[2];
    const float* b1 = (const float*)d_in[3];
    const float* W2 = (const float*)d_in[4];
    const float* b2 = (const float*)d_in[5];
    const float* W3 = (const float*)d_in[6];
    const float* b3 = (const float*)d_in[7];
    float* out = (float*)d_out;

    static bool attr_set = false;
    if (!attr_set) {
        cudaFuncSetAttribute(mlp_persist, cudaFuncAttributeMaxDynamicSharedMemorySize,
                             (int)SMEM_BYTES);
        attr_set = true;
    }

    mlp_persist<<<GRID, NT, SMEM_BYTES>>>(feat, labels, W1, b1, W2, b2, W3, b3);
    lambda_kernel<<<8 * BB, 256>>>(out);
}

// round 17
// speedup vs baseline: 1.6148x; 1.0018x over previous
#include <cuda_runtime.h>
#include <cuda_fp16.h>
#include <math.h>
#include <stdint.h>

#define BB 256
#define NN 256
#define DD 136
#define HH 128
#define ROWS (BB*NN)

#define K1PAD 152
#define K2PAD 136
#define TM    64
#define NT    256
#define GRID  296
#define NTILES (ROWS / TM)   // 1024

// ---------------- scratch globals ----------------
__device__ __align__(16) float4 g_elg[ROWS];        // {exp(s), 1+log2(1+s), 2^label, 0}
__device__ __align__(16) __half g_W1t[HH * K1PAD];
__device__ __align__(16) __half g_W2t[HH * K2PAD];
__device__ unsigned long long g_bar = 0ULL;         // monotonic grid barrier

// ---------------- smem layout ----------------
#define A_BYTES  (TM * K1PAD * 2)           // 19456
#define W1_BYTES (128 * K1PAD * 2)
#define W2_BYTES (128 * K2PAD * 2)
#define OFF_A    0
#define OFF_W1   (A_BYTES)
#define OFF_W2   (OFF_W1 + W1_BYTES)
#define OFF_B1   (OFF_W2 + W2_BYTES)        // 93184
#define OFF_B2   (OFF_B1 + 512)
#define OFF_W3   (OFF_B2 + 512)
#define OFF_RED  (OFF_W3 + 512)
#define SMEM_BYTES (OFF_RED + 512)          // 95232 (x2 CTAs < 227KB)

__device__ __forceinline__ uint32_t smem_u32(const void* p) {
    uint32_t a;
    asm("{ .reg .u64 t; cvta.to.shared.u64 t, %1; cvt.u32.u64 %0, t; }" : "=r"(a) : "l"(p));
    return a;
}
__device__ __forceinline__ void cp_async16(uint32_t dst, const void* src) {
    asm volatile("cp.async.cg.shared.global [%0], [%1], 16;" :: "r"(dst), "l"(src));
}
#define CP_COMMIT() asm volatile("cp.async.commit_group;" ::: "memory")
#define CP_WAIT0()  asm volatile("cp.async.wait_group 0;" ::: "memory")
#define GROUP_BAR(g) asm volatile("bar.sync %0, 64;" :: "r"(1 + (g)) : "memory")

__device__ __forceinline__ void ldsm_x4(uint32_t* r, uint32_t addr) {
    asm volatile("ldmatrix.sync.aligned.m8n8.x4.shared.b16 {%0,%1,%2,%3}, [%4];"
        : "=r"(r[0]), "=r"(r[1]), "=r"(r[2]), "=r"(r[3]) : "r"(addr));
}
__device__ __forceinline__ void mma16816(float* d, const uint32_t* a, uint32_t b0, uint32_t b1) {
    asm volatile("mma.sync.aligned.m16n8k16.row.col.f32.f16.f16.f32 "
        "{%0,%1,%2,%3}, {%4,%5,%6,%7}, {%8,%9}, {%0,%1,%2,%3};"
        : "+f"(d[0]), "+f"(d[1]), "+f"(d[2]), "+f"(d[3])
        : "r"(a[0]), "r"(a[1]), "r"(a[2]), "r"(a[3]), "r"(b0), "r"(b1));
}
__device__ __forceinline__ uint32_t pack_h2(float x, float y) {
    __half h0 = __float2half_rn(x), h1 = __float2half_rn(y);
    return ((uint32_t)__half_as_ushort(h1) << 16) | __half_as_ushort(h0);
}

// ---------------- persistent fused MLP with group-scoped barriers ----------------
__global__ __launch_bounds__(NT, 2)
void mlp_persist(const float* __restrict__ feat, const int* __restrict__ labels,
                 const float* __restrict__ W1, const float* __restrict__ b1,
                 const float* __restrict__ W2, const float* __restrict__ b2,
                 const float* __restrict__ W3, const float* __restrict__ b3)
{
    extern __shared__ char smem[];
    __half* A  = (__half*)(smem + OFF_A);
    float* sB1 = (float*)(smem + OFF_B1);
    float* sB2 = (float*)(smem + OFF_B2);
    float* sW3 = (float*)(smem + OFF_W3);
    float* red = (float*)(smem + OFF_RED);

    const int tid  = threadIdx.x;
    const int lane = tid & 31;
    const int wid  = tid >> 5;
    const int grp  = wid >> 1;               // m-group 0..3
    const int m0    = grp * 16;
    const int nside = (wid & 1) * 64;

    const uint32_t uA  = smem_u32(smem + OFF_A);
    const uint32_t uW1 = smem_u32(smem + OFF_W1);
    const uint32_t uW2 = smem_u32(smem + OFF_W2);

    const int a_row = m0 + (lane & 7) + ((lane >> 3) & 1) * 8;
    const int a_kof = (lane >> 4) * 8;
    const int w_rof = (lane & 7) + (lane >> 4) * 8;
    const int w_kof = ((lane >> 3) & 1) * 8;

    // ===== phase 0: weight prep (grid-strided), then global barrier =====
    for (int idx = blockIdx.x * NT + tid; idx < 152 * 32 + 128 * 32; idx += GRID * NT) {
        if (idx < 152 * 32) {
            int k = idx >> 5, nq = (idx & 31) * 4;
            float4 v = (k < DD) ? *(const float4*)(W1 + k * HH + nq)
                                : make_float4(0.f, 0.f, 0.f, 0.f);
            g_W1t[(nq + 0) * K1PAD + k] = __float2half_rn(v.x);
            g_W1t[(nq + 1) * K1PAD + k] = __float2half_rn(v.y);
            g_W1t[(nq + 2) * K1PAD + k] = __float2half_rn(v.z);
            g_W1t[(nq + 3) * K1PAD + k] = __float2half_rn(v.w);
        } else {
            int idx2 = idx - 152 * 32;
            int k = idx2 >> 5, nq = (idx2 & 31) * 4;
            float4 v = *(const float4*)(W2 + k * HH + nq);
            g_W2t[(nq + 0) * K2PAD + k] = __float2half_rn(v.x);
            g_W2t[(nq + 1) * K2PAD + k] = __float2half_rn(v.y);
            g_W2t[(nq + 2) * K2PAD + k] = __float2half_rn(v.z);
            g_W2t[(nq + 3) * K2PAD + k] = __float2half_rn(v.w);
        }
    }
    __threadfence();
    __syncthreads();
    if (tid == 0) {
        unsigned long long old = atomicAdd(&g_bar, 1ULL);
        unsigned long long target = (old / GRID + 1ULL) * GRID;
        unsigned long long v;
        do {
            asm volatile("ld.acquire.gpu.global.u64 %0, [%1];" : "=l"(v) : "l"(&g_bar));
        } while (v < target);
    }
    __syncthreads();

    // ===== stage weights to smem ONCE =====
    {
        const char* s;
        s = (const char*)g_W1t;
        for (int i = tid; i < W1_BYTES / 16; i += NT) cp_async16(uW1 + i * 16, s + i * 16);
        s = (const char*)g_W2t;
        for (int i = tid; i < W2_BYTES / 16; i += NT) cp_async16(uW2 + i * 16, s + i * 16);
        CP_COMMIT();
    }
    if (tid < 128) { sB1[tid] = b1[tid]; sB2[tid] = b2[tid]; sW3[tid] = W3[tid]; }
    const float b3v = __ldg(b3);
    CP_WAIT0();
    __syncthreads();   // last full-CTA sync: weights + biases resident

    // ===== pipelined persistent tile loop (group-scoped barriers) =====
    const int r  = tid >> 2;        // staging row: group stages its own rows
    const int c4 = tid & 3;
    float2 v[17];
    {   // initial prefetch
        const float* fb = feat + ((long)blockIdx.x * TM + r) * DD + 2 * c4;
        #pragma unroll
        for (int it = 0; it < 17; it++) v[it] = *(const float2*)(fb + 8 * it);
    }

    for (int tile = blockIdx.x; tile < NTILES; tile += GRID) {
        const long row0 = (long)tile * TM;

        // ---- store prefetched features -> fp16 A (group rows only) ----
        #pragma unroll
        for (int it = 0; it < 17; it++) {
            const int p = c4 + 4 * it;
            *(uint32_t*)(A + r * K1PAD + 2 * p) = pack_h2(v[it].x, v[it].y);
        }
        *(uint32_t*)(A + r * K1PAD + 2 * (68 + c4)) = 0;
        *(uint32_t*)(A + r * K1PAD + 2 * (72 + c4)) = 0;
        GROUP_BAR(grp);

        // ---- prefetch next tile's features ----
        {
            const int nxt = tile + GRID;
            if (nxt < NTILES) {
                const float* fb = feat + ((long)nxt * TM + r) * DD + 2 * c4;
                #pragma unroll
                for (int it = 0; it < 17; it++) v[it] = *(const float2*)(fb + 8 * it);
            }
        }

        float acc[8][4];
        #pragma unroll
        for (int t = 0; t < 8; t++)
            #pragma unroll
            for (int q = 0; q < 4; q++) acc[t][q] = 0.f;

        // ---- layer 1: 9 ksteps ----
        #pragma unroll
        for (int ks = 0; ks < 9; ks++) {
            const int k0 = ks * 16;
            uint32_t a[4];
            ldsm_x4(a, uA + (a_row * K1PAD + k0 + a_kof) * 2);
            #pragma unroll
            for (int np = 0; np < 4; np++) {
                const int n0 = nside + np * 16;
                uint32_t w[4];
                ldsm_x4(w, uW1 + ((n0 + w_rof) * K1PAD + k0 + w_kof) * 2);
                mma16816(acc[2*np],   a, w[0], w[1]);
                mma16816(acc[2*np+1], a, w[2], w[3]);
            }
        }
        GROUP_BAR(grp);    // partner's layer-1 A reads complete

        // ---- epilogue 1: relu(+b1) -> fp16 into A (group rows), stride K2PAD ----
        {
            const int rA = m0 + (lane >> 2);
            #pragma unroll
            for (int nt = 0; nt < 8; nt++) {
                const int c = nside + nt * 8 + (lane & 3) * 2;
                float v0 = fmaxf(acc[nt][0] + sB1[c],     0.f);
                float v1 = fmaxf(acc[nt][1] + sB1[c + 1], 0.f);
                float v2 = fmaxf(acc[nt][2] + sB1[c],     0.f);
                float v3 = fmaxf(acc[nt][3] + sB1[c + 1], 0.f);
                *(uint32_t*)(A + rA * K2PAD + c)       = pack_h2(v0, v1);
                *(uint32_t*)(A + (rA + 8) * K2PAD + c) = pack_h2(v2, v3);
            }
        }
        GROUP_BAR(grp);    // h1 rows visible to both group warps

        #pragma unroll
        for (int t = 0; t < 8; t++)
            #pragma unroll
            for (int q = 0; q < 4; q++) acc[t][q] = 0.f;

        // ---- layer 2: 8 ksteps ----
        #pragma unroll
        for (int ks = 0; ks < 8; ks++) {
            const int k0 = ks * 16;
            uint32_t a[4];
            ldsm_x4(a, uA + (a_row * K2PAD + k0 + a_kof) * 2);
            #pragma unroll
            for (int np = 0; np < 4; np++) {
                const int n0 = nside + np * 16;
                uint32_t w[4];
                ldsm_x4(w, uW2 + ((n0 + w_rof) * K2PAD + k0 + w_kof) * 2);
                mma16816(acc[2*np],   a, w[0], w[1]);
                mma16816(acc[2*np+1], a, w[2], w[3]);
            }
        }

        // ---- epilogue 2: relu(+b2).W3, reduce into group-local red ----
        {
            float pl = 0.f, ph = 0.f;
            #pragma unroll
            for (int nt = 0; nt < 8; nt++) {
                const int c = nside + nt * 8 + (lane & 3) * 2;
                pl = fmaf(fmaxf(acc[nt][0] + sB2[c],     0.f), sW3[c],     pl);
                pl = fmaf(fmaxf(acc[nt][1] + sB2[c + 1], 0.f), sW3[c + 1], pl);
                ph = fmaf(fmaxf(acc[nt][2] + sB2[c],     0.f), sW3[c],     ph);
                ph = fmaf(fmaxf(acc[nt][3] + sB2[c + 1], 0.f), sW3[c + 1], ph);
            }
            pl += __shfl_xor_sync(0xFFFFFFFF, pl, 1);
            pl += __shfl_xor_sync(0xFFFFFFFF, pl, 2);
            ph += __shfl_xor_sync(0xFFFFFFFF, ph, 1);
            ph += __shfl_xor_sync(0xFFFFFFFF, ph, 2);
            if ((lane & 3) == 0) {
                const int rr = m0 + (lane >> 2);
                red[rr * 2 + (wid & 1)]       = pl;
                red[(rr + 8) * 2 + (wid & 1)] = ph;
            }
        }
        GROUP_BAR(grp);    // red complete for this group

        // ---- score + elg write: even warp of the group, lanes 0..15 ----
        if (((wid & 1) == 0) && lane < 16) {
            const int row = m0 + lane;
            float s = red[row * 2] + red[row * 2 + 1] + b3v;
            int   l = labels[row0 + row];
            float e = __expf(s);
            float M = 1.0f + __log2f(1.0f + s);
            float g = __int_as_float((l + 127) << 23);   // 2^l exactly
            g_elg[row0 + row] = make_float4(e, M, g, 0.f);
        }
        // no further barrier needed: next feature store touches A only; next
        // red overwrite is 3 group-barriers away, ordering the red reads above.
    }
}

// ---------------- lambda kernel: 8 blocks/batch, 4-pair fraction combine ----------------
__global__ __launch_bounds__(256, 8)
void lambda_kernel(float* __restrict__ out)
{
    __shared__ float4 elg[NN];
    __shared__ float  part[256];

    const int bid   = blockIdx.x;        // 0..2047
    const int batch = bid >> 3;
    const int io    = bid & 7;
    const int tid   = threadIdx.x;
    const int il    = tid & 31;
    const int jh    = tid >> 5;

    elg[tid] = g_elg[batch * NN + tid];
    __syncthreads();

    const int i = io * 32 + il;
    const float4 me = elg[i];
    const float ei = me.x, Mi = me.y, gi = me.z;

    float acc = 0.f;
    const int j0 = jh * 32;
    #pragma unroll 2
    for (int j = 0; j < 32; j += 4) {
        float4 v0 = elg[j0 + j];
        float4 v1 = elg[j0 + j + 1];
        float4 v2 = elg[j0 + j + 2];
        float4 v3 = elg[j0 + j + 3];
        float sg0 = gi - v0.z, sg1 = gi - v1.z, sg2 = gi - v2.z, sg3 = gi - v3.z;
        float n0 = sg0 * ((sg0 > 0.f) ? ei : v0.x);
        float n1 = sg1 * ((sg1 > 0.f) ? ei : v1.x);
        float n2 = sg2 * ((sg2 > 0.f) ? ei : v2.x);
        float n3 = sg3 * ((sg3 > 0.f) ? ei : v3.x);
        float d0 = fabsf(fmaxf(Mi, v0.y)) * (ei + v0.x);
        float d1 = fabsf(fmaxf(Mi, v1.y)) * (ei + v1.x);
        float d2 = fabsf(fmaxf(Mi, v2.y)) * (ei + v2.x);
        float d3 = fabsf(fmaxf(Mi, v3.y)) * (ei + v3.x);
        float d01 = d0 * d1, d23 = d2 * d3;
        float t01 = fmaf(n0, d1, n1 * d0);
        float t23 = fmaf(n2, d3, n3 * d2);
        float num = fmaf(t01, d23, t23 * d01);
        float den = d01 * d23;
        acc += __fdividef(num, den);
    }
    part[tid] = acc;
    __syncthreads();
    if (tid < 32) {
        float s = 0.f;
        #pragma unroll
        for (int k = 0; k < 8; k++) s += part[tid + 32 * k];
        out[batch * NN + io * 32 + tid] = 0.5f * s;
    }
}

extern "C" void kernel_launch(void* const* d_in, const int* in_sizes, int n_in,
                              void* d_out, int out_size)
{
    const float* feat   = (const float*)d_in[0];
    const int*   labels = (const int*)d_in[1];
    const float* W1 = (const float*)d_in[2];
    const float* b1 = (const float*)d_in[3];
    const float* W2 = (const float*)d_in[4];
    const float* b2 = (const float*)d_in[5];
    const float* W3 = (const float*)d_in[6];
    const float* b3 = (const float*)d_in[7];
    float* out = (float*)d_out;

    static bool attr_set = false;
    if (!attr_set) {
        cudaFuncSetAttribute(mlp_persist, cudaFuncAttributeMaxDynamicSharedMemorySize,
                             (int)SMEM_BYTES);
        attr_set = true;
    }

    mlp_persist<<<GRID, NT, SMEM_BYTES>>>(feat, labels, W1, b1, W2, b2, W3, b3);
    lambda_kernel<<<8 * BB, 256>>>(out);
}